// round 11
// baseline (speedup 1.0000x reference)
#include <cuda_runtime.h>
#include <math.h>

// Fully-fused Sherman–Morrison delta-rule update (single launch).
// out[b,o,:] = W[b,o,:] - scale_b * (W[b,o,:]·x_b - g[b,o]) * x_b
// scale_b = 1/(1024 + softplus(x_b·eta_w + eta_b))
//
// 256-thread blocks, one warp per output row, grid 16384.
// x_b AND eta_w are staged into smem in one prologue (single barrier).
// Each warp then computes BOTH dots in one fused loop — W LDG interleaved
// with xs/es LDS FMAs — so after the staging sync all 8 warps run fully
// independently: no cross-warp coupling anywhere on the streaming path.
__global__ __launch_bounds__(256) void sm_update_fused_kernel(
    const float* __restrict__ W,
    const float* __restrict__ x,
    const float* __restrict__ grad,
    const float* __restrict__ eta_w,
    const float* __restrict__ eta_b,
    float* __restrict__ out) {

    __shared__ float4 xs[256];   // x_b: 1024 floats
    __shared__ float4 es[256];   // eta_w: 1024 floats

    const int b = blockIdx.x >> 7;        // 128 blocks per batch
    const int ochunk = blockIdx.x & 127;
    const int t = threadIdx.x;
    const int warp = t >> 5;
    const int lane = t & 31;

    const float ebias = eta_b[0];

    // stage x_b and eta_w (the only barrier in the kernel)
    xs[t] = reinterpret_cast<const float4*>(x + (size_t)b * 1024)[t];
    es[t] = reinterpret_cast<const float4*>(eta_w)[t];
    __syncthreads();

    const int o = (ochunk << 3) + warp;
    const size_t row_off = ((size_t)b * 1024 + o) * 1024;
    const float4* wrow = reinterpret_cast<const float4*>(W + row_off);

    const float g = grad[(size_t)b * 1024 + o];

    // fused loop: W LDG interleaved with (dot, eta) FMAs from smem
    float4 wv[8];
    float dot = 0.0f;
    float ep = 0.0f;
#pragma unroll
    for (int k = 0; k < 8; k++) {
        const int idx = (k << 5) + lane;
        wv[k] = wrow[idx];
        const float4 xv = xs[idx];
        const float4 ew = es[idx];
        dot += wv[k].x * xv.x + wv[k].y * xv.y + wv[k].z * xv.z + wv[k].w * xv.w;
        ep  += ew.x * xv.x + ew.y * xv.y + ew.z * xv.z + ew.w * xv.w;
    }
    for (int off = 16; off; off >>= 1) {
        dot += __shfl_xor_sync(0xffffffffu, dot, off);
        ep  += __shfl_xor_sync(0xffffffffu, ep,  off);
    }

    // per-warp scale: softplus computed redundantly (8x/block — free)
    const float z = ep + ebias;
    const float sp = fmaxf(z, 0.0f) + log1pf(expf(-fabsf(z)));
    const float scale = 1.0f / (1024.0f + sp);

    const float se = scale * (dot - g);

    float4* orow = reinterpret_cast<float4*>(out + row_off);
#pragma unroll
    for (int k = 0; k < 8; k++) {
        const int idx = (k << 5) + lane;
        const float4 xv = xs[idx];
        float4 r;
        r.x = wv[k].x - se * xv.x;
        r.y = wv[k].y - se * xv.y;
        r.z = wv[k].z - se * xv.z;
        r.w = wv[k].w - se * xv.w;
        orow[idx] = r;
    }
}

extern "C" void kernel_launch(void* const* d_in, const int* in_sizes, int n_in,
                              void* d_out, int out_size) {
    // metadata order: W_t [128,1024,1024], x_t [128,1024], grad_l_in [128,1024],
    //                 eta_w [1,1024], eta_b [1]
    const float* W     = (const float*)d_in[0];
    const float* x     = (const float*)d_in[1];
    const float* grad  = (const float*)d_in[2];
    const float* eta_w = (const float*)d_in[3];
    const float* eta_b = (const float*)d_in[4];
    float* out = (float*)d_out;

    sm_update_fused_kernel<<<128 * 128, 256>>>(W, x, grad, eta_w, eta_b, out);
}

// round 12
// speedup vs baseline: 1.0227x; 1.0227x over previous
#include <cuda_runtime.h>
#include <math.h>

// Fully-fused Sherman–Morrison delta-rule update (single launch).
// out[b,o,:] = W[b,o,:] - scale_b * (W[b,o,:]·x_b - g[b,o]) * x_b
// scale_b = 1/(1024 + softplus(x_b·eta_w + eta_b))
//
// 256-thread blocks, one warp per output row, grid 16384.
// KEY ORDERING: both barriers complete BEFORE any W load is issued — the
// eta partials are published to red[] in the (cheap, smem-only) prologue,
// so the entire long-latency phase (W load -> dot -> per-warp softplus ->
// store) runs with ZERO cross-warp coupling, exactly like the proven
// standalone streaming kernel, but in one fused launch.
__global__ __launch_bounds__(256) void sm_update_fused_kernel(
    const float* __restrict__ W,
    const float* __restrict__ x,
    const float* __restrict__ grad,
    const float* __restrict__ eta_w,
    const float* __restrict__ eta_b,
    float* __restrict__ out) {

    __shared__ float4 xs[256];   // x_b: 1024 floats
    __shared__ float red[8];

    const int b = blockIdx.x >> 7;        // 128 blocks per batch
    const int ochunk = blockIdx.x & 127;
    const int t = threadIdx.x;
    const int warp = t >> 5;
    const int lane = t & 31;

    const float ebias = eta_b[0];

    // ---- prologue (all barriers live here; no W loads yet) ----
    xs[t] = reinterpret_cast<const float4*>(x + (size_t)b * 1024)[t];
    __syncthreads();
    {
        const float4 ew = reinterpret_cast<const float4*>(eta_w)[t];
        const float4 xv = xs[t];
        float p = xv.x * ew.x + xv.y * ew.y + xv.z * ew.z + xv.w * ew.w;
        for (int off = 16; off; off >>= 1)
            p += __shfl_xor_sync(0xffffffffu, p, off);
        if (lane == 0) red[warp] = p;
    }
    __syncthreads();   // red[] published; nothing below ever syncs again

    // ---- fully decoupled per-warp streaming phase ----
    const int o = (ochunk << 3) + warp;
    const size_t row_off = ((size_t)b * 1024 + o) * 1024;
    const float4* wrow = reinterpret_cast<const float4*>(W + row_off);

    const float g = grad[(size_t)b * 1024 + o];

    float4 wv[8];
    float dot = 0.0f;
#pragma unroll
    for (int k = 0; k < 8; k++) {
        const int idx = (k << 5) + lane;
        wv[k] = wrow[idx];
        const float4 xv = xs[idx];
        dot += wv[k].x * xv.x + wv[k].y * xv.y + wv[k].z * xv.z + wv[k].w * xv.w;
    }
    for (int off = 16; off; off >>= 1)
        dot += __shfl_xor_sync(0xffffffffu, dot, off);

    // per-warp scale finish (red[] already published; barrier-free)
    float s = red[lane & 7];
    s += __shfl_xor_sync(0xffffffffu, s, 4);
    s += __shfl_xor_sync(0xffffffffu, s, 2);
    s += __shfl_xor_sync(0xffffffffu, s, 1);
    const float z = s + ebias;
    const float sp = fmaxf(z, 0.0f) + log1pf(expf(-fabsf(z)));
    const float scale = 1.0f / (1024.0f + sp);

    const float se = scale * (dot - g);

    float4* orow = reinterpret_cast<float4*>(out + row_off);
#pragma unroll
    for (int k = 0; k < 8; k++) {
        const int idx = (k << 5) + lane;
        const float4 xv = xs[idx];
        float4 r;
        r.x = wv[k].x - se * xv.x;
        r.y = wv[k].y - se * xv.y;
        r.z = wv[k].z - se * xv.z;
        r.w = wv[k].w - se * xv.w;
        orow[idx] = r;
    }
}

extern "C" void kernel_launch(void* const* d_in, const int* in_sizes, int n_in,
                              void* d_out, int out_size) {
    // metadata order: W_t [128,1024,1024], x_t [128,1024], grad_l_in [128,1024],
    //                 eta_w [1,1024], eta_b [1]
    const float* W     = (const float*)d_in[0];
    const float* x     = (const float*)d_in[1];
    const float* grad  = (const float*)d_in[2];
    const float* eta_w = (const float*)d_in[3];
    const float* eta_b = (const float*)d_in[4];
    float* out = (float*)d_out;

    sm_update_fused_kernel<<<128 * 128, 256>>>(W, x, grad, eta_w, eta_b, out);
}

// round 13
// speedup vs baseline: 1.0251x; 1.0024x over previous
#include <cuda_runtime.h>
#include <math.h>

// Fully-fused Sherman–Morrison delta-rule update (single launch).
// out[b,o,:] = W[b,o,:] - scale_b * (W[b,o,:]·x_b - g[b,o]) * x_b
// scale_b = 1/(1024 + softplus(x_b·eta_w + eta_b))
//
// Converged configuration (12 rounds of measurement):
//  - 256-thread blocks, one warp per output row, grid 16384
//  - interleaved float4 W-load + dot FMA (MLP=8) — front-batched loads,
//    wider blocks, multi-row warps, and in-loop eta fusion all measured slower
//  - eta partials published to red[]; barrier AFTER the W loop (best regs/occ)
//  - per-warp scale finish: 3 shfls + redundant softplus, no t0 serialization
//  - plain loads; __stcs on the write-once output stream
__global__ __launch_bounds__(256) void sm_update_fused_kernel(
    const float* __restrict__ W,
    const float* __restrict__ x,
    const float* __restrict__ grad,
    const float* __restrict__ eta_w,
    const float* __restrict__ eta_b,
    float* __restrict__ out) {

    __shared__ float4 xs[256];   // x_b: 1024 floats
    __shared__ float red[8];

    const int b = blockIdx.x >> 7;        // 128 blocks per batch
    const int ochunk = blockIdx.x & 127;
    const int t = threadIdx.x;
    const int warp = t >> 5;
    const int lane = t & 31;

    const float ebias = eta_b[0];

    // stage x_b
    xs[t] = reinterpret_cast<const float4*>(x + (size_t)b * 1024)[t];
    __syncthreads();

    // eta partial: dot(x_b, eta_w), 4 elems/thread (4KB, L2-resident)
    {
        const float4 ew = reinterpret_cast<const float4*>(eta_w)[t];
        const float4 xv = xs[t];
        float p = xv.x * ew.x + xv.y * ew.y + xv.z * ew.z + xv.w * ew.w;
        for (int off = 16; off; off >>= 1)
            p += __shfl_xor_sync(0xffffffffu, p, off);
        if (lane == 0) red[warp] = p;
    }

    // W row: interleaved load + FMA (long-latency phase; overlaps reduction)
    const int o = (ochunk << 3) + warp;
    const size_t row_off = ((size_t)b * 1024 + o) * 1024;
    const float4* wrow = reinterpret_cast<const float4*>(W + row_off);

    const float g = grad[(size_t)b * 1024 + o];

    float4 wv[8];
    float dot = 0.0f;
#pragma unroll
    for (int k = 0; k < 8; k++) {
        const int idx = (k << 5) + lane;
        wv[k] = wrow[idx];
        const float4 xv = xs[idx];
        dot += wv[k].x * xv.x + wv[k].y * xv.y + wv[k].z * xv.z + wv[k].w * xv.w;
    }
    for (int off = 16; off; off >>= 1)
        dot += __shfl_xor_sync(0xffffffffu, dot, off);

    // per-warp scale finish
    __syncthreads();               // red[] complete (only remaining barrier)
    float s = red[lane & 7];
    s += __shfl_xor_sync(0xffffffffu, s, 4);
    s += __shfl_xor_sync(0xffffffffu, s, 2);
    s += __shfl_xor_sync(0xffffffffu, s, 1);
    const float z = s + ebias;
    const float sp = fmaxf(z, 0.0f) + log1pf(expf(-fabsf(z)));
    const float scale = 1.0f / (1024.0f + sp);

    const float se = scale * (dot - g);

    float4* orow = reinterpret_cast<float4*>(out + row_off);
#pragma unroll
    for (int k = 0; k < 8; k++) {
        const int idx = (k << 5) + lane;
        const float4 xv = xs[idx];
        float4 r;
        r.x = wv[k].x - se * xv.x;
        r.y = wv[k].y - se * xv.y;
        r.z = wv[k].z - se * xv.z;
        r.w = wv[k].w - se * xv.w;
        __stcs(orow + idx, r);     // write-once output: streaming store
    }
}

extern "C" void kernel_launch(void* const* d_in, const int* in_sizes, int n_in,
                              void* d_out, int out_size) {
    // metadata order: W_t [128,1024,1024], x_t [128,1024], grad_l_in [128,1024],
    //                 eta_w [1,1024], eta_b [1]
    const float* W     = (const float*)d_in[0];
    const float* x     = (const float*)d_in[1];
    const float* grad  = (const float*)d_in[2];
    const float* eta_w = (const float*)d_in[3];
    const float* eta_b = (const float*)d_in[4];
    float* out = (float*)d_out;

    sm_update_fused_kernel<<<128 * 128, 256>>>(W, x, grad, eta_w, eta_b, out);
}